// round 1
// baseline (speedup 1.0000x reference)
#include <cuda_runtime.h>
#include <math.h>
#include <stdint.h>

// ---------------- problem constants ----------------
#define TSTEPS 80
#define BATCH  64
#define FDIM   4096
#define EDIM   512
#define HDIM   512
#define VDIM   13000
#define GDIM   (4*HDIM)   // 2048
#define NSTEPS (2*TSTEPS) // 160
#define START_ID 1

// ---------------- scratch (static device, no allocs) ----------------
__device__ __align__(16) float g_emb   [TSTEPS*BATCH*EDIM];          // (b*80+t, 512)
__device__ __align__(16) float g_decemb[TSTEPS*BATCH*EDIM];          // (t*64+b, 512)
__device__ __align__(16) float g_xgate [NSTEPS*BATCH*GDIM];          // (s*64+b, 2048) incl. b_ih+b_hh
__device__ __align__(16) float g_hhist [TSTEPS*BATCH*HDIM];          // (t*64+b, 512) decoder h
__device__ __align__(16) float g_hbuf  [2][BATCH*HDIM];              // h ping-pong, (b,512)
__device__ unsigned g_bar_cnt;
__device__ unsigned g_bar_gen;

// ---------------- generic fp32 GEMM: C = A(MxK) * B(N x ldb, slice koff..)^T + bias ----------------
// BM=128, BN=64, BK=16, 256 threads, 8x4 register tile.
#define BM 128
#define BN 64
#define BK 16

__global__ __launch_bounds__(256) void gemm_kernel(
    const float* __restrict__ A, int lda, int remapA,
    const float* __restrict__ B, int ldb, int koff,
    const float* __restrict__ bias1, const float* __restrict__ bias2,
    float* __restrict__ C, int M, int N, int K, int outRemap)
{
    __shared__ float As[BK][BM + 4];
    __shared__ float Bs[BK][BN + 4];

    const int tid = threadIdx.x;
    const int n0  = blockIdx.x * BN;
    const int m0  = blockIdx.y * BM;
    const int tx  = tid & 15;   // n dir, 4 cols each
    const int ty  = tid >> 4;   // m dir, 8 rows each

    float acc[8][4];
#pragma unroll
    for (int i = 0; i < 8; i++)
#pragma unroll
        for (int j = 0; j < 4; j++) acc[i][j] = 0.f;

    for (int k0 = 0; k0 < K; k0 += BK) {
        // load A tile: 128x16 = 512 float4, 2 per thread
#pragma unroll
        for (int u = 0; u < 2; u++) {
            int f   = tid * 2 + u;
            int row = f >> 2;
            int kq  = f & 3;
            int m   = m0 + row;
            int arow = remapA ? ((m & 63) * 80 + (m >> 6)) : m;
            float4 v = *(const float4*)(A + (size_t)arow * lda + k0 + kq * 4);
            As[kq*4+0][row] = v.x;
            As[kq*4+1][row] = v.y;
            As[kq*4+2][row] = v.z;
            As[kq*4+3][row] = v.w;
        }
        // load B tile: 64x16 = 256 float4, 1 per thread
        {
            int row = tid >> 2;
            int kq  = tid & 3;
            int n   = n0 + row;
            float4 v = make_float4(0.f, 0.f, 0.f, 0.f);
            if (n < N) v = *(const float4*)(B + (size_t)n * ldb + koff + k0 + kq * 4);
            Bs[kq*4+0][row] = v.x;
            Bs[kq*4+1][row] = v.y;
            Bs[kq*4+2][row] = v.z;
            Bs[kq*4+3][row] = v.w;
        }
        __syncthreads();

#pragma unroll
        for (int k = 0; k < BK; k++) {
            float4 a0 = *(const float4*)&As[k][ty * 8];
            float4 a1 = *(const float4*)&As[k][ty * 8 + 4];
            float4 b0 = *(const float4*)&Bs[k][tx * 4];
            float a[8] = {a0.x, a0.y, a0.z, a0.w, a1.x, a1.y, a1.z, a1.w};
            float bb[4] = {b0.x, b0.y, b0.z, b0.w};
#pragma unroll
            for (int i = 0; i < 8; i++)
#pragma unroll
                for (int j = 0; j < 4; j++)
                    acc[i][j] += a[i] * bb[j];
        }
        __syncthreads();
    }

    // epilogue
    float bv[4];
#pragma unroll
    for (int j = 0; j < 4; j++) {
        int n = n0 + tx * 4 + j;
        float b = 0.f;
        if (n < N) {
            b = bias1[n];
            if (bias2) b += bias2[n];
        }
        bv[j] = b;
    }
#pragma unroll
    for (int i = 0; i < 8; i++) {
        int m = m0 + ty * 8 + i;
        size_t base = outRemap ? (size_t)((m & 63) * 80 + (m >> 6)) * (size_t)N
                               : (size_t)m * (size_t)N;
#pragma unroll
        for (int j = 0; j < 4; j++) {
            int n = n0 + tx * 4 + j;
            if (n < N) C[base + n] = acc[i][j] + bv[j];
        }
    }
}

// ---------------- decoder word-embedding gather (t-major rows) ----------------
__global__ void gather_dec_kernel(const int* __restrict__ labels,
                                  const float* __restrict__ embed,
                                  float* __restrict__ out)
{
    int r = blockIdx.x;            // r = t*64 + b
    int t = r >> 6, b = r & 63;
    int id = (t == 0) ? START_ID : labels[b * TSTEPS + (t - 1)];
    const float4* src = (const float4*)(embed + (size_t)id * EDIM);
    float4* dst = (float4*)(out + (size_t)r * EDIM);
    dst[threadIdx.x] = src[threadIdx.x];   // 128 threads x float4 = 512 floats
}

// ---------------- persistent LSTM recurrence ----------------
#define RCTAS 128
#define RTHREADS 128
#define HS_STRIDE 515   // 512 + 3 pad -> stride % 32 == 3, conflict-free strided access

__device__ __forceinline__ void grid_sync(int nctas)
{
    __syncthreads();
    if (threadIdx.x == 0) {
        __threadfence();
        unsigned gen = *(volatile unsigned*)&g_bar_gen;
        if (atomicAdd(&g_bar_cnt, 1u) == (unsigned)(nctas - 1)) {
            *(volatile unsigned*)&g_bar_cnt = 0u;
            __threadfence();
            *(volatile unsigned*)&g_bar_gen = gen + 1u;
        } else {
            while (*(volatile unsigned*)&g_bar_gen == gen) { }
        }
    }
    __syncthreads();
}

__device__ __forceinline__ float sigf(float x) { return 1.f / (1.f + expf(-x)); }

__global__ __launch_bounds__(RTHREADS, 1) void lstm_kernel(
    const float* __restrict__ Whh,
    const float* __restrict__ xgate,
    float* __restrict__ hhist)
{
    extern __shared__ float smem[];
    float* ws = smem;                 // 16 rows x 512
    float* hs = smem + 16 * 512;      // 64 x HS_STRIDE

    const int tid = threadIdx.x;
    const int ct  = blockIdx.x;
    const int hl  = tid >> 5;         // 0..3 (hidden unit within CTA)
    const int bg  = tid & 31;
    const int hu  = ct * 4 + hl;      // global hidden unit
    const int b0  = bg, b1 = bg + 32;

    // load this CTA's 16 W_hh rows: local row r = g*4 + hr -> global row g*512 + ct*4 + hr
    for (int i = tid; i < 16 * 512; i += RTHREADS) {
        int r = i >> 9, k = i & 511;
        int g = r >> 2, hr = r & 3;
        ws[i] = Whh[(size_t)(g * 512 + ct * 4 + hr) * 512 + k];
    }
    // zero h buffer 0
    for (int i = blockIdx.x * RTHREADS + tid; i < BATCH * HDIM; i += RCTAS * RTHREADS)
        g_hbuf[0][i] = 0.f;

    float c0 = 0.f, c1 = 0.f;
    grid_sync(RCTAS);

    int cur = 0;
    for (int s = 0; s < NSTEPS; s++) {
        // stage full h (64x512) into SMEM; __ldcg to bypass stale L1
        const float4* hb4 = (const float4*)g_hbuf[cur];
        for (int i = tid; i < (BATCH * HDIM) / 4; i += RTHREADS) {
            float4 v = __ldcg(hb4 + i);
            int b = i >> 7;
            int kq = (i & 127) << 2;
            float* d = hs + b * HS_STRIDE + kq;
            d[0] = v.x; d[1] = v.y; d[2] = v.z; d[3] = v.w;
        }
        __syncthreads();

        const float* xg = xgate + (size_t)s * BATCH * GDIM;
        float acc[4][2];
#pragma unroll
        for (int g = 0; g < 4; g++) {
            acc[g][0] = xg[b0 * GDIM + g * 512 + hu];
            acc[g][1] = xg[b1 * GDIM + g * 512 + hu];
        }

        const float* h0p = hs + b0 * HS_STRIDE;
        const float* h1p = hs + b1 * HS_STRIDE;
        const float* w0 = ws + (0 * 4 + hl) * 512;
        const float* w1 = ws + (1 * 4 + hl) * 512;
        const float* w2 = ws + (2 * 4 + hl) * 512;
        const float* w3 = ws + (3 * 4 + hl) * 512;

#pragma unroll 4
        for (int k = 0; k < 512; k++) {
            float hv0 = h0p[k], hv1 = h1p[k];
            float wi = w0[k], wf = w1[k], wg = w2[k], wo = w3[k];
            acc[0][0] += hv0 * wi;  acc[0][1] += hv1 * wi;
            acc[1][0] += hv0 * wf;  acc[1][1] += hv1 * wf;
            acc[2][0] += hv0 * wg;  acc[2][1] += hv1 * wg;
            acc[3][0] += hv0 * wo;  acc[3][1] += hv1 * wo;
        }

        // elementwise LSTM cell (gate order i,f,g,o)
        float i0 = sigf(acc[0][0]), f0 = sigf(acc[1][0]);
        float gg0 = tanhf(acc[2][0]), o0 = sigf(acc[3][0]);
        c0 = f0 * c0 + i0 * gg0;
        float h0v = o0 * tanhf(c0);

        float i1 = sigf(acc[0][1]), f1 = sigf(acc[1][1]);
        float gg1 = tanhf(acc[2][1]), o1 = sigf(acc[3][1]);
        c1 = f1 * c1 + i1 * gg1;
        float h1v = o1 * tanhf(c1);

        float* hn = g_hbuf[cur ^ 1];
        hn[b0 * HDIM + hu] = h0v;
        hn[b1 * HDIM + hu] = h1v;
        if (s >= TSTEPS) {
            size_t t = s - TSTEPS;
            hhist[(t * BATCH + b0) * HDIM + hu] = h0v;
            hhist[(t * BATCH + b1) * HDIM + hu] = h1v;
        }

        grid_sync(RCTAS);
        cur ^= 1;
    }
}

// ---------------- launch ----------------
extern "C" void kernel_launch(void* const* d_in, const int* in_sizes, int n_in,
                              void* d_out, int out_size)
{
    const float* feats    = (const float*)d_in[0];   // (64,80,4096)
    const int*   labels   = (const int*)  d_in[1];   // (64,80)
    const float* W_frame  = (const float*)d_in[2];   // (512,4096)
    const float* b_frame  = (const float*)d_in[3];   // (512)
    const float* embed    = (const float*)d_in[4];   // (13000,512)
    const float* W_ih     = (const float*)d_in[5];   // (2048,1024)
    const float* W_hh     = (const float*)d_in[6];   // (2048,512)
    const float* b_ih     = (const float*)d_in[7];   // (2048)
    const float* b_hh     = (const float*)d_in[8];   // (2048)
    const float* W_out    = (const float*)d_in[9];   // (13000,512)
    const float* b_out    = (const float*)d_in[10];  // (13000)
    float* out = (float*)d_out;                      // (64,80,13000)

    // device scratch addresses
    float *p_emb, *p_decemb, *p_xgate, *p_hhist;
    cudaGetSymbolAddress((void**)&p_emb,    g_emb);
    cudaGetSymbolAddress((void**)&p_decemb, g_decemb);
    cudaGetSymbolAddress((void**)&p_xgate,  g_xgate);
    cudaGetSymbolAddress((void**)&p_hhist,  g_hhist);

    const int smem_lstm = (16 * 512 + BATCH * HS_STRIDE) * sizeof(float);
    cudaFuncSetAttribute(lstm_kernel, cudaFuncAttributeMaxDynamicSharedMemorySize, smem_lstm);

    const int M = TSTEPS * BATCH;  // 5120

    // 1) frame embedding: emb(b*80+t, 512) = feats @ W_frame^T + b_frame
    {
        dim3 grid(EDIM / BN, M / BM);
        gemm_kernel<<<grid, 256>>>(feats, FDIM, 0, W_frame, FDIM, 0,
                                   b_frame, nullptr, p_emb, M, EDIM, FDIM, 0);
    }
    // 2) encoder x-gates: xgate[s=0..79] = emb(remapped to t-major) @ W_ih[:, :512]^T + b_ih + b_hh
    {
        dim3 grid(GDIM / BN, M / BM);
        gemm_kernel<<<grid, 256>>>(p_emb, EDIM, 1, W_ih, EDIM + EDIM, 0,
                                   b_ih, b_hh, p_xgate, M, GDIM, EDIM, 0);
    }
    // 3) decoder word embeddings (t-major)
    gather_dec_kernel<<<M, 128>>>(labels, embed, p_decemb);
    // 4) decoder x-gates: xgate[s=80..159] = decemb @ W_ih[:, 512:]^T + b_ih + b_hh
    {
        dim3 grid(GDIM / BN, M / BM);
        gemm_kernel<<<grid, 256>>>(p_decemb, EDIM, 0, W_ih, EDIM + EDIM, EDIM,
                                   b_ih, b_hh, p_xgate + (size_t)TSTEPS * BATCH * GDIM,
                                   M, GDIM, EDIM, 0);
    }
    // 5) 160-step recurrence (persistent, grid-synced)
    lstm_kernel<<<RCTAS, RTHREADS, smem_lstm>>>(W_hh, p_xgate, p_hhist);
    // 6) logits: out[b,t,v] = hhist(t*64+b) @ W_out^T + b_out
    {
        dim3 grid((VDIM + BN - 1) / BN, M / BM);
        gemm_kernel<<<grid, 256>>>(p_hhist, HDIM, 0, W_out, HDIM, 0,
                                   b_out, nullptr, out, M, VDIM, HDIM, 1);
    }
}

// round 2
// speedup vs baseline: 1.0005x; 1.0005x over previous
#include <cuda_runtime.h>
#include <math.h>
#include <stdint.h>

// ---------------- problem constants ----------------
#define TSTEPS 80
#define BATCH  64
#define FDIM   4096
#define EDIM   512
#define HDIM   512
#define VDIM   13000
#define GDIM   (4*HDIM)   // 2048
#define NSTEPS (2*TSTEPS) // 160
#define START_ID 1

// ---------------- scratch (static device, no allocs) ----------------
__device__ __align__(16) float g_emb   [TSTEPS*BATCH*EDIM];          // (b*80+t, 512)
__device__ __align__(16) float g_decemb[TSTEPS*BATCH*EDIM];          // (t*64+b, 512)
__device__ __align__(16) float g_xgate [NSTEPS*BATCH*GDIM];          // (s*64+b, 2048) incl. b_ih+b_hh
__device__ __align__(16) float g_hhist [TSTEPS*BATCH*HDIM];          // (t*64+b, 512) decoder h
__device__ __align__(16) float g_hbuf  [2][BATCH*HDIM];              // h ping-pong, (b,512)
__device__ unsigned g_bar_cnt;
__device__ unsigned g_bar_gen;

// ---------------- generic fp32 GEMM: C = A(MxK) * B(N x ldb, slice koff..)^T + bias ----------------
// BM=128, BN=64, BK=16, 256 threads, 8x4 register tile.
#define BM 128
#define BN 64
#define BK 16

__global__ __launch_bounds__(256) void gemm_kernel(
    const float* __restrict__ A, int lda, int remapA,
    const float* __restrict__ B, int ldb, int koff,
    const float* __restrict__ bias1, const float* __restrict__ bias2,
    float* __restrict__ C, int M, int N, int K, int outRemap)
{
    __shared__ float As[BK][BM + 4];
    __shared__ float Bs[BK][BN + 4];

    const int tid = threadIdx.x;
    const int n0  = blockIdx.x * BN;
    const int m0  = blockIdx.y * BM;
    const int tx  = tid & 15;   // n dir, 4 cols each
    const int ty  = tid >> 4;   // m dir, 8 rows each

    float acc[8][4];
#pragma unroll
    for (int i = 0; i < 8; i++)
#pragma unroll
        for (int j = 0; j < 4; j++) acc[i][j] = 0.f;

    for (int k0 = 0; k0 < K; k0 += BK) {
        // load A tile: 128x16 = 512 float4, 2 per thread
#pragma unroll
        for (int u = 0; u < 2; u++) {
            int f   = tid * 2 + u;
            int row = f >> 2;
            int kq  = f & 3;
            int m   = m0 + row;
            int arow = remapA ? ((m & 63) * 80 + (m >> 6)) : m;
            float4 v = *(const float4*)(A + (size_t)arow * lda + k0 + kq * 4);
            As[kq*4+0][row] = v.x;
            As[kq*4+1][row] = v.y;
            As[kq*4+2][row] = v.z;
            As[kq*4+3][row] = v.w;
        }
        // load B tile: 64x16 = 256 float4, 1 per thread
        {
            int row = tid >> 2;
            int kq  = tid & 3;
            int n   = n0 + row;
            float4 v = make_float4(0.f, 0.f, 0.f, 0.f);
            if (n < N) v = *(const float4*)(B + (size_t)n * ldb + koff + k0 + kq * 4);
            Bs[kq*4+0][row] = v.x;
            Bs[kq*4+1][row] = v.y;
            Bs[kq*4+2][row] = v.z;
            Bs[kq*4+3][row] = v.w;
        }
        __syncthreads();

#pragma unroll
        for (int k = 0; k < BK; k++) {
            float4 a0 = *(const float4*)&As[k][ty * 8];
            float4 a1 = *(const float4*)&As[k][ty * 8 + 4];
            float4 b0 = *(const float4*)&Bs[k][tx * 4];
            float a[8] = {a0.x, a0.y, a0.z, a0.w, a1.x, a1.y, a1.z, a1.w};
            float bb[4] = {b0.x, b0.y, b0.z, b0.w};
#pragma unroll
            for (int i = 0; i < 8; i++)
#pragma unroll
                for (int j = 0; j < 4; j++)
                    acc[i][j] += a[i] * bb[j];
        }
        __syncthreads();
    }

    // epilogue
    float bv[4];
#pragma unroll
    for (int j = 0; j < 4; j++) {
        int n = n0 + tx * 4 + j;
        float b = 0.f;
        if (n < N) {
            b = bias1[n];
            if (bias2) b += bias2[n];
        }
        bv[j] = b;
    }
#pragma unroll
    for (int i = 0; i < 8; i++) {
        int m = m0 + ty * 8 + i;
        size_t base = outRemap ? (size_t)((m & 63) * 80 + (m >> 6)) * (size_t)N
                               : (size_t)m * (size_t)N;
#pragma unroll
        for (int j = 0; j < 4; j++) {
            int n = n0 + tx * 4 + j;
            if (n < N) C[base + n] = acc[i][j] + bv[j];
        }
    }
}

// ---------------- decoder word-embedding gather (t-major rows) ----------------
__global__ void gather_dec_kernel(const int* __restrict__ labels,
                                  const float* __restrict__ embed,
                                  float* __restrict__ out)
{
    int r = blockIdx.x;            // r = t*64 + b
    int t = r >> 6, b = r & 63;
    int id = (t == 0) ? START_ID : labels[b * TSTEPS + (t - 1)];
    const float4* src = (const float4*)(embed + (size_t)id * EDIM);
    float4* dst = (float4*)(out + (size_t)r * EDIM);
    dst[threadIdx.x] = src[threadIdx.x];   // 128 threads x float4 = 512 floats
}

// ---------------- persistent LSTM recurrence ----------------
#define RCTAS 128
#define RTHREADS 128
#define HS_STRIDE 515   // 512 + 3 pad -> stride % 32 == 3, conflict-free strided access

__device__ __forceinline__ void grid_sync(int nctas)
{
    __syncthreads();
    if (threadIdx.x == 0) {
        __threadfence();
        unsigned gen = *(volatile unsigned*)&g_bar_gen;
        if (atomicAdd(&g_bar_cnt, 1u) == (unsigned)(nctas - 1)) {
            *(volatile unsigned*)&g_bar_cnt = 0u;
            __threadfence();
            *(volatile unsigned*)&g_bar_gen = gen + 1u;
        } else {
            while (*(volatile unsigned*)&g_bar_gen == gen) { }
        }
    }
    __syncthreads();
}

__device__ __forceinline__ float sigf(float x) { return 1.f / (1.f + expf(-x)); }

__global__ __launch_bounds__(RTHREADS, 1) void lstm_kernel(
    const float* __restrict__ Whh,
    const float* __restrict__ xgate,
    float* __restrict__ hhist)
{
    extern __shared__ float smem[];
    float* ws = smem;                 // 16 rows x 512
    float* hs = smem + 16 * 512;      // 64 x HS_STRIDE

    const int tid = threadIdx.x;
    const int ct  = blockIdx.x;
    const int hl  = tid >> 5;         // 0..3 (hidden unit within CTA)
    const int bg  = tid & 31;
    const int hu  = ct * 4 + hl;      // global hidden unit
    const int b0  = bg, b1 = bg + 32;

    // load this CTA's 16 W_hh rows: local row r = g*4 + hr -> global row g*512 + ct*4 + hr
    for (int i = tid; i < 16 * 512; i += RTHREADS) {
        int r = i >> 9, k = i & 511;
        int g = r >> 2, hr = r & 3;
        ws[i] = Whh[(size_t)(g * 512 + ct * 4 + hr) * 512 + k];
    }
    // zero h buffer 0
    for (int i = blockIdx.x * RTHREADS + tid; i < BATCH * HDIM; i += RCTAS * RTHREADS)
        g_hbuf[0][i] = 0.f;

    float c0 = 0.f, c1 = 0.f;
    grid_sync(RCTAS);

    int cur = 0;
    for (int s = 0; s < NSTEPS; s++) {
        // stage full h (64x512) into SMEM; __ldcg to bypass stale L1
        const float4* hb4 = (const float4*)g_hbuf[cur];
        for (int i = tid; i < (BATCH * HDIM) / 4; i += RTHREADS) {
            float4 v = __ldcg(hb4 + i);
            int b = i >> 7;
            int kq = (i & 127) << 2;
            float* d = hs + b * HS_STRIDE + kq;
            d[0] = v.x; d[1] = v.y; d[2] = v.z; d[3] = v.w;
        }
        __syncthreads();

        const float* xg = xgate + (size_t)s * BATCH * GDIM;
        float acc[4][2];
#pragma unroll
        for (int g = 0; g < 4; g++) {
            acc[g][0] = xg[b0 * GDIM + g * 512 + hu];
            acc[g][1] = xg[b1 * GDIM + g * 512 + hu];
        }

        const float* h0p = hs + b0 * HS_STRIDE;
        const float* h1p = hs + b1 * HS_STRIDE;
        const float* w0 = ws + (0 * 4 + hl) * 512;
        const float* w1 = ws + (1 * 4 + hl) * 512;
        const float* w2 = ws + (2 * 4 + hl) * 512;
        const float* w3 = ws + (3 * 4 + hl) * 512;

#pragma unroll 4
        for (int k = 0; k < 512; k++) {
            float hv0 = h0p[k], hv1 = h1p[k];
            float wi = w0[k], wf = w1[k], wg = w2[k], wo = w3[k];
            acc[0][0] += hv0 * wi;  acc[0][1] += hv1 * wi;
            acc[1][0] += hv0 * wf;  acc[1][1] += hv1 * wf;
            acc[2][0] += hv0 * wg;  acc[2][1] += hv1 * wg;
            acc[3][0] += hv0 * wo;  acc[3][1] += hv1 * wo;
        }

        // elementwise LSTM cell (gate order i,f,g,o)
        float i0 = sigf(acc[0][0]), f0 = sigf(acc[1][0]);
        float gg0 = tanhf(acc[2][0]), o0 = sigf(acc[3][0]);
        c0 = f0 * c0 + i0 * gg0;
        float h0v = o0 * tanhf(c0);

        float i1 = sigf(acc[0][1]), f1 = sigf(acc[1][1]);
        float gg1 = tanhf(acc[2][1]), o1 = sigf(acc[3][1]);
        c1 = f1 * c1 + i1 * gg1;
        float h1v = o1 * tanhf(c1);

        float* hn = g_hbuf[cur ^ 1];
        hn[b0 * HDIM + hu] = h0v;
        hn[b1 * HDIM + hu] = h1v;
        if (s >= TSTEPS) {
            size_t t = s - TSTEPS;
            hhist[(t * BATCH + b0) * HDIM + hu] = h0v;
            hhist[(t * BATCH + b1) * HDIM + hu] = h1v;
        }

        grid_sync(RCTAS);
        cur ^= 1;
    }
}

// ---------------- launch ----------------
extern "C" void kernel_launch(void* const* d_in, const int* in_sizes, int n_in,
                              void* d_out, int out_size)
{
    const float* feats    = (const float*)d_in[0];   // (64,80,4096)
    const int*   labels   = (const int*)  d_in[1];   // (64,80)
    const float* W_frame  = (const float*)d_in[2];   // (512,4096)
    const float* b_frame  = (const float*)d_in[3];   // (512)
    const float* embed    = (const float*)d_in[4];   // (13000,512)
    const float* W_ih     = (const float*)d_in[5];   // (2048,1024)
    const float* W_hh     = (const float*)d_in[6];   // (2048,512)
    const float* b_ih     = (const float*)d_in[7];   // (2048)
    const float* b_hh     = (const float*)d_in[8];   // (2048)
    const float* W_out    = (const float*)d_in[9];   // (13000,512)
    const float* b_out    = (const float*)d_in[10];  // (13000)
    float* out = (float*)d_out;                      // (64,80,13000)

    // device scratch addresses
    float *p_emb, *p_decemb, *p_xgate, *p_hhist;
    cudaGetSymbolAddress((void**)&p_emb,    g_emb);
    cudaGetSymbolAddress((void**)&p_decemb, g_decemb);
    cudaGetSymbolAddress((void**)&p_xgate,  g_xgate);
    cudaGetSymbolAddress((void**)&p_hhist,  g_hhist);

    const int smem_lstm = (16 * 512 + BATCH * HS_STRIDE) * sizeof(float);
    cudaFuncSetAttribute(lstm_kernel, cudaFuncAttributeMaxDynamicSharedMemorySize, smem_lstm);

    const int M = TSTEPS * BATCH;  // 5120

    // 1) frame embedding: emb(b*80+t, 512) = feats @ W_frame^T + b_frame
    {
        dim3 grid(EDIM / BN, M / BM);
        gemm_kernel<<<grid, 256>>>(feats, FDIM, 0, W_frame, FDIM, 0,
                                   b_frame, nullptr, p_emb, M, EDIM, FDIM, 0);
    }
    // 2) encoder x-gates: xgate[s=0..79] = emb(remapped to t-major) @ W_ih[:, :512]^T + b_ih + b_hh
    {
        dim3 grid(GDIM / BN, M / BM);
        gemm_kernel<<<grid, 256>>>(p_emb, EDIM, 1, W_ih, EDIM + EDIM, 0,
                                   b_ih, b_hh, p_xgate, M, GDIM, EDIM, 0);
    }
    // 3) decoder word embeddings (t-major)
    gather_dec_kernel<<<M, 128>>>(labels, embed, p_decemb);
    // 4) decoder x-gates: xgate[s=80..159] = decemb @ W_ih[:, 512:]^T + b_ih + b_hh
    {
        dim3 grid(GDIM / BN, M / BM);
        gemm_kernel<<<grid, 256>>>(p_decemb, EDIM, 0, W_ih, EDIM + EDIM, EDIM,
                                   b_ih, b_hh, p_xgate + (size_t)TSTEPS * BATCH * GDIM,
                                   M, GDIM, EDIM, 0);
    }
    // 5) 160-step recurrence (persistent, grid-synced)
    lstm_kernel<<<RCTAS, RTHREADS, smem_lstm>>>(W_hh, p_xgate, p_hhist);
    // 6) logits: out[b,t,v] = hhist(t*64+b) @ W_out^T + b_out
    {
        dim3 grid((VDIM + BN - 1) / BN, M / BM);
        gemm_kernel<<<grid, 256>>>(p_hhist, HDIM, 0, W_out, HDIM, 0,
                                   b_out, nullptr, out, M, VDIM, HDIM, 1);
    }
}

// round 4
// speedup vs baseline: 1.7250x; 1.7243x over previous
#include <cuda_runtime.h>
#include <cuda_bf16.h>
#include <math.h>
#include <stdint.h>

#define TSTEPS 80
#define BATCH  64
#define FDIM   4096
#define EDIM   512
#define HDIM   512
#define VDIM   13000
#define VPAD   13056
#define GDIM   2048
#define NSTEPS 160
#define MROWS  5120
#define K2     1536
#define START_ID 1

// ---------------- scratch ----------------
__device__ __align__(16) float g_emb   [MROWS*EDIM];
__device__ __align__(16) float g_decemb[MROWS*EDIM];
__device__ __align__(16) float g_xgate [(size_t)NSTEPS*GDIM*BATCH];  // [s][n][b]
__device__ __align__(16) float g_hhist [MROWS*HDIM];                  // rows t*64+b
__device__ __align__(16) float g_hbuf  [2][BATCH*HDIM];
__device__ __align__(16) __nv_bfloat16 g_hh2[(size_t)MROWS*K2];
__device__ __align__(16) __nv_bfloat16 g_Wo2[(size_t)VPAD*K2];
__device__ unsigned g_bar_cnt, g_bar_gen;

// ---------------- generic-PTX helpers (no sm_103a-only features) ----------------
__device__ __forceinline__ uint32_t s2u(const void* p) {
    uint32_t a;
    asm("{ .reg .u64 t; cvta.to.shared.u64 t, %1; cvt.u32.u64 %0, t; }" : "=r"(a) : "l"(p));
    return a;
}
__device__ __forceinline__ void cpasync16(uint32_t dst, const void* src) {
    asm volatile("cp.async.cg.shared.global [%0], [%1], 16;" :: "r"(dst), "l"(src));
}
__device__ __forceinline__ void ldm4(uint32_t* d, uint32_t addr) {
    asm volatile("ldmatrix.sync.aligned.m8n8.x4.shared.b16 {%0,%1,%2,%3}, [%4];"
        : "=r"(d[0]), "=r"(d[1]), "=r"(d[2]), "=r"(d[3]) : "r"(addr));
}
__device__ __forceinline__ void mma16816(float* c, const uint32_t* a, const uint32_t* b) {
    asm volatile("mma.sync.aligned.m16n8k16.row.col.f32.bf16.bf16.f32 "
        "{%0,%1,%2,%3}, {%4,%5,%6,%7}, {%8,%9}, {%0,%1,%2,%3};"
        : "+f"(c[0]), "+f"(c[1]), "+f"(c[2]), "+f"(c[3])
        : "r"(a[0]), "r"(a[1]), "r"(a[2]), "r"(a[3]), "r"(b[0]), "r"(b[1]));
}
__device__ __forceinline__ void fma2(unsigned long long& acc,
                                     unsigned long long a, unsigned long long b) {
    asm("fma.rn.f32x2 %0, %1, %2, %0;" : "+l"(acc) : "l"(a), "l"(b));
}

// ---------------- fp32 GEMM (embed + xgates), proven ----------------
#define BM 128
#define BN 64
#define BK 16
__global__ __launch_bounds__(256) void gemm_kernel(
    const float* __restrict__ A, int lda, int remapA,
    const float* __restrict__ B, int ldb, int koff,
    const float* __restrict__ bias1, const float* __restrict__ bias2,
    float* __restrict__ C, int M, int N, int K, int outMode)
{
    __shared__ float As[BK][BM + 4];
    __shared__ float Bs[BK][BN + 4];
    const int tid = threadIdx.x;
    const int n0 = blockIdx.x * BN, m0 = blockIdx.y * BM;
    const int tx = tid & 15, ty = tid >> 4;
    float acc[8][4];
#pragma unroll
    for (int i = 0; i < 8; i++)
#pragma unroll
        for (int j = 0; j < 4; j++) acc[i][j] = 0.f;

    for (int k0 = 0; k0 < K; k0 += BK) {
#pragma unroll
        for (int u = 0; u < 2; u++) {
            int f = tid * 2 + u, row = f >> 2, kq = f & 3;
            int m = m0 + row;
            int ar = remapA ? ((m & 63) * 80 + (m >> 6)) : m;
            float4 v = *(const float4*)(A + (size_t)ar * lda + k0 + kq * 4);
            As[kq*4+0][row] = v.x; As[kq*4+1][row] = v.y;
            As[kq*4+2][row] = v.z; As[kq*4+3][row] = v.w;
        }
        {
            int row = tid >> 2, kq = tid & 3, n = n0 + row;
            float4 v = make_float4(0.f, 0.f, 0.f, 0.f);
            if (n < N) v = *(const float4*)(B + (size_t)n * ldb + koff + k0 + kq * 4);
            Bs[kq*4+0][row] = v.x; Bs[kq*4+1][row] = v.y;
            Bs[kq*4+2][row] = v.z; Bs[kq*4+3][row] = v.w;
        }
        __syncthreads();
#pragma unroll
        for (int k = 0; k < BK; k++) {
            float4 a0 = *(const float4*)&As[k][ty*8];
            float4 a1 = *(const float4*)&As[k][ty*8+4];
            float4 b0 = *(const float4*)&Bs[k][tx*4];
            float a[8] = {a0.x,a0.y,a0.z,a0.w,a1.x,a1.y,a1.z,a1.w};
            float bb[4] = {b0.x,b0.y,b0.z,b0.w};
#pragma unroll
            for (int i = 0; i < 8; i++)
#pragma unroll
                for (int j = 0; j < 4; j++) acc[i][j] += a[i] * bb[j];
        }
        __syncthreads();
    }
    float bv[4];
#pragma unroll
    for (int j = 0; j < 4; j++) {
        int n = n0 + tx*4 + j;
        float b = 0.f;
        if (n < N) { b = bias1[n]; if (bias2) b += bias2[n]; }
        bv[j] = b;
    }
#pragma unroll
    for (int i = 0; i < 8; i++) {
        int m = m0 + ty*8 + i;
        if (outMode == 2) {   // xgate transposed: C[s][n][b], s=m>>6, b=m&63
            float* bp = C + (size_t)(m >> 6) * (GDIM*BATCH) + (m & 63);
#pragma unroll
            for (int j = 0; j < 4; j++) {
                int n = n0 + tx*4 + j;
                bp[(size_t)n * 64] = acc[i][j] + bv[j];
            }
        } else {
            size_t base = (size_t)m * (size_t)N;
#pragma unroll
            for (int j = 0; j < 4; j++) {
                int n = n0 + tx*4 + j;
                if (n < N) C[base + n] = acc[i][j] + bv[j];
            }
        }
    }
}

// ---------------- decoder gather ----------------
__global__ void gather_dec_kernel(const int* __restrict__ labels,
                                  const float* __restrict__ embed, float* __restrict__ out)
{
    int r = blockIdx.x, t = r >> 6, b = r & 63;
    int id = (t == 0) ? START_ID : labels[b * TSTEPS + (t - 1)];
    ((float4*)(out + (size_t)r * EDIM))[threadIdx.x] =
        ((const float4*)(embed + (size_t)id * EDIM))[threadIdx.x];
}

// ---------------- fp32 -> 3-seg split-bf16 (K 512 -> 1536) ----------------
// loSeg=2: [hi|hi|lo] (A side); loSeg=1: [hi|lo|hi] (B side). rows>=rows_src zeroed.
__global__ void split3_kernel(const float* __restrict__ src, __nv_bfloat16* __restrict__ dst,
                              int rows_src, int loSeg)
{
    int i = blockIdx.x * 256 + threadIdx.x;
    int r = i >> 7, c4 = (i & 127) << 2;
    __nv_bfloat16 hi[4], lo[4];
    if (r < rows_src) {
        float4 v = *(const float4*)(src + (size_t)r * 512 + c4);
        float vv[4] = {v.x, v.y, v.z, v.w};
#pragma unroll
        for (int j = 0; j < 4; j++) {
            hi[j] = __float2bfloat16(vv[j]);
            lo[j] = __float2bfloat16(vv[j] - __bfloat162float(hi[j]));
        }
    } else {
        __nv_bfloat16 z = __float2bfloat16(0.f);
#pragma unroll
        for (int j = 0; j < 4; j++) { hi[j] = z; lo[j] = z; }
    }
    __nv_bfloat16* d = dst + (size_t)r * K2;
    int hOff = (loSeg == 2) ? 512 : 1024, lOff = (loSeg == 2) ? 1024 : 512;
    *(uint64_t*)(d + c4)        = *(const uint64_t*)hi;
    *(uint64_t*)(d + hOff + c4) = *(const uint64_t*)hi;
    *(uint64_t*)(d + lOff + c4) = *(const uint64_t*)lo;
}

// ---------------- mma.sync bf16 logits GEMM ----------------
// out(5120x13000, remapped rows) = hh2(5120xK2) @ Wo2(13056xK2)^T + bias
// CTA tile 128x128, K-chunk 64, double-buffered cp.async, xor-swizzled smem.
#define NC    (K2/64)
#define BUFSZ 32768          // A 16KB + B 16KB per stage

__device__ __forceinline__ void ld_chunk(uint32_t sbase,
    const __nv_bfloat16* __restrict__ A, const __nv_bfloat16* __restrict__ B,
    int m0, int n0, int c, int tid)
{
    const __nv_bfloat16* ap = A + (size_t)m0 * K2 + c * 64;
    const __nv_bfloat16* bp = B + (size_t)n0 * K2 + c * 64;
#pragma unroll
    for (int u = 0; u < 4; u++) {
        int idx = u * 256 + tid, r = idx >> 3, q = idx & 7;
        cpasync16(sbase + r * 128 + ((q ^ (r & 7)) << 4), ap + (size_t)r * K2 + q * 8);
    }
#pragma unroll
    for (int u = 0; u < 4; u++) {
        int idx = u * 256 + tid, r = idx >> 3, q = idx & 7;
        cpasync16(sbase + 16384 + r * 128 + ((q ^ (r & 7)) << 4), bp + (size_t)r * K2 + q * 8);
    }
}

__global__ __launch_bounds__(256) void mma_tc(
    const __nv_bfloat16* __restrict__ A, const __nv_bfloat16* __restrict__ B,
    const float* __restrict__ bias, float* __restrict__ C)
{
    extern __shared__ char smc[];
    const uint32_t sbase = s2u(smc);
    const int tid = threadIdx.x, lane = tid & 31, wid = tid >> 5;
    const int wm = wid & 3, wn = wid >> 2;        // warp tile 32 x 64
    const int n0 = blockIdx.x * 128, m0 = blockIdx.y * 128;

    float acc[2][8][4];
#pragma unroll
    for (int a = 0; a < 2; a++)
#pragma unroll
        for (int b = 0; b < 8; b++)
#pragma unroll
            for (int d = 0; d < 4; d++) acc[a][b][d] = 0.f;

    ld_chunk(sbase, A, B, m0, n0, 0, tid);
    asm volatile("cp.async.commit_group;" ::: "memory");

    for (int c = 0; c < NC; c++) {
        if (c + 1 < NC) {
            ld_chunk(sbase + ((c + 1) & 1) * BUFSZ, A, B, m0, n0, c + 1, tid);
            asm volatile("cp.async.commit_group;" ::: "memory");
            asm volatile("cp.async.wait_group 1;" ::: "memory");
        } else {
            asm volatile("cp.async.wait_group 0;" ::: "memory");
        }
        __syncthreads();

        const uint32_t sa = sbase + (c & 1) * BUFSZ;
        const uint32_t sb = sa + 16384;
#pragma unroll
        for (int ks = 0; ks < 4; ks++) {
            uint32_t af[2][4];
#pragma unroll
            for (int mt = 0; mt < 2; mt++) {
                int r = wm * 32 + mt * 16 + (lane & 15);
                int q = 2 * ks + (lane >> 4);
                ldm4(af[mt], sa + r * 128 + ((q ^ (r & 7)) << 4));
            }
            uint32_t bf[4][4];
#pragma unroll
            for (int bp2 = 0; bp2 < 4; bp2++) {
                int r = wn * 64 + (bp2 * 2 + (lane >> 4)) * 8 + (lane & 7);
                int q = 2 * ks + ((lane >> 3) & 1);
                ldm4(bf[bp2], sb + r * 128 + ((q ^ (r & 7)) << 4));
            }
#pragma unroll
            for (int mt = 0; mt < 2; mt++)
#pragma unroll
                for (int nt = 0; nt < 8; nt++)
                    mma16816(acc[mt][nt], af[mt], &bf[nt >> 1][(nt & 1) * 2]);
        }
        __syncthreads();
    }

    // epilogue: c-frag (c0,c1)=row tq cols 2tr..+1; (c2,c3)=row tq+8
    const int mb = m0 + wm * 32, nb = n0 + wn * 64;
#pragma unroll
    for (int mt = 0; mt < 2; mt++)
#pragma unroll
        for (int half = 0; half < 2; half++) {
            int r = mb + mt * 16 + (lane >> 2) + half * 8;
            float* op = C + (size_t)((r & 63) * 80 + (r >> 6)) * VDIM;
#pragma unroll
            for (int nt = 0; nt < 8; nt++) {
                int cb = nb + nt * 8 + (lane & 3) * 2;
                if (cb < VDIM) {
                    float2 bv = *(const float2*)(bias + cb);
                    float2 v;
                    v.x = acc[mt][nt][half * 2 + 0] + bv.x;
                    v.y = acc[mt][nt][half * 2 + 1] + bv.y;
                    *(float2*)(op + cb) = v;
                }
            }
        }
}

// ---------------- persistent LSTM (f32x2, k-parity accumulators) ----------------
#define RCTAS 128
#define HPAD  516   // floats per batch row in smem (conflict-free, 16B aligned)

__device__ __forceinline__ void grid_sync()
{
    __syncthreads();
    if (threadIdx.x == 0) {
        __threadfence();
        unsigned gen = *(volatile unsigned*)&g_bar_gen;
        if (atomicAdd(&g_bar_cnt, 1u) == RCTAS - 1) {
            *(volatile unsigned*)&g_bar_cnt = 0u;
            __threadfence();
            *(volatile unsigned*)&g_bar_gen = gen + 1u;
        } else {
            while (*(volatile unsigned*)&g_bar_gen == gen) { }
        }
    }
    __syncthreads();
}
__device__ __forceinline__ float sigf(float x) { return 1.f / (1.f + expf(-x)); }

__global__ __launch_bounds__(256, 1) void lstm_kernel(
    const float* __restrict__ Whh, const float* __restrict__ xg,
    float* __restrict__ hhist)
{
    extern __shared__ float sm[];
    float* ws = sm;                 // [8 hu][4 gate][512 k]
    float* hs = sm + 8 * 4 * 512;   // [32 b][HPAD]

    const int tid = threadIdx.x;
    const int b_l = tid & 31, hu_l = tid >> 5;
    const int ct_b = blockIdx.x & 1, ct_h = blockIdx.x >> 1;
    const int hu = ct_h * 8 + hu_l, b = ct_b * 32 + b_l;

    for (int i = tid; i < 8 * 4 * 512; i += 256) {
        int h = i >> 11, g = (i >> 9) & 3, k = i & 511;
        ws[i] = Whh[(size_t)(g * 512 + ct_h * 8 + h) * 512 + k];
    }
    {
        int i = blockIdx.x * 256 + tid;   // exactly covers 32768
        g_hbuf[0][i] = 0.f;
    }
    float cc = 0.f;
    grid_sync();

    int cur = 0;
    for (int s = 0; s < NSTEPS; s++) {
        // stage this CTA's 32-batch h slice
        const float4* src = (const float4*)(g_hbuf[cur] + (size_t)ct_b * 32 * 512);
#pragma unroll
        for (int j = 0; j < 16; j++) {
            int idx = tid + j * 256;
            float4 v = __ldcg(src + idx);
            int bb = idx >> 7, kq = (idx & 127) << 2;
            *(float4*)(hs + bb * HPAD + kq) = v;
        }
        __syncthreads();

        const float* xb = xg + (size_t)s * (GDIM * BATCH) + ct_b * 32 + b_l;
        float x0 = xb[(size_t)(hu)        * 64];
        float x1 = xb[(size_t)(512  + hu) * 64];
        float x2 = xb[(size_t)(1024 + hu) * 64];
        float x3 = xb[(size_t)(1536 + hu) * 64];

        unsigned long long a0 = 0ull, a1 = 0ull, a2 = 0ull, a3 = 0ull;
        const longlong2* hp = (const longlong2*)(hs + b_l * HPAD);
        const longlong2* w0 = (const longlong2*)(ws + (hu_l * 4 + 0) * 512);
        const longlong2* w1 = (const longlong2*)(ws + (hu_l * 4 + 1) * 512);
        const longlong2* w2 = (const longlong2*)(ws + (hu_l * 4 + 2) * 512);
        const longlong2* w3 = (const longlong2*)(ws + (hu_l * 4 + 3) * 512);
#pragma unroll 4
        for (int k4 = 0; k4 < 128; k4++) {
            longlong2 h2 = hp[k4];
            longlong2 w;
            w = w0[k4];
            fma2(a0, (unsigned long long)h2.x, (unsigned long long)w.x);
            fma2(a0, (unsigned long long)h2.y, (unsigned long long)w.y);
            w = w1[k4];
            fma2(a1, (unsigned long long)h2.x, (unsigned long long)w.x);
            fma2(a1, (unsigned long long)h2.y, (unsigned long long)w.y);
            w = w2[k4];
            fma2(a2, (unsigned long long)h2.x, (unsigned long long)w.x);
            fma2(a2, (unsigned long long)h2.y, (unsigned long long)w.y);
            w = w3[k4];
            fma2(a3, (unsigned long long)h2.x, (unsigned long long)w.x);
            fma2(a3, (unsigned long long)h2.y, (unsigned long long)w.y);
        }
        float lo, hi, gi, gf, gg, go;
        asm("mov.b64 {%0,%1}, %2;" : "=f"(lo), "=f"(hi) : "l"(a0)); gi = lo + hi + x0;
        asm("mov.b64 {%0,%1}, %2;" : "=f"(lo), "=f"(hi) : "l"(a1)); gf = lo + hi + x1;
        asm("mov.b64 {%0,%1}, %2;" : "=f"(lo), "=f"(hi) : "l"(a2)); gg = lo + hi + x2;
        asm("mov.b64 {%0,%1}, %2;" : "=f"(lo), "=f"(hi) : "l"(a3)); go = lo + hi + x3;

        float iv = sigf(gi), fv = sigf(gf), gv = tanhf(gg), ov = sigf(go);
        cc = fv * cc + iv * gv;
        float hv = ov * tanhf(cc);

        g_hbuf[cur ^ 1][(size_t)b * 512 + hu] = hv;
        if (s >= TSTEPS)
            hhist[(size_t)((s - TSTEPS) * 64 + b) * 512 + hu] = hv;

        grid_sync();
        cur ^= 1;
    }
}

// ---------------- launch ----------------
extern "C" void kernel_launch(void* const* d_in, const int* in_sizes, int n_in,
                              void* d_out, int out_size)
{
    const float* feats   = (const float*)d_in[0];
    const int*   labels  = (const int*)  d_in[1];
    const float* W_frame = (const float*)d_in[2];
    const float* b_frame = (const float*)d_in[3];
    const float* embed   = (const float*)d_in[4];
    const float* W_ih    = (const float*)d_in[5];
    const float* W_hh    = (const float*)d_in[6];
    const float* b_ih    = (const float*)d_in[7];
    const float* b_hh    = (const float*)d_in[8];
    const float* W_out   = (const float*)d_in[9];
    const float* b_out   = (const float*)d_in[10];
    float* out = (float*)d_out;

    float *p_emb, *p_decemb, *p_xgate, *p_hhist;
    __nv_bfloat16 *p_hh2, *p_Wo2;
    cudaGetSymbolAddress((void**)&p_emb,    g_emb);
    cudaGetSymbolAddress((void**)&p_decemb, g_decemb);
    cudaGetSymbolAddress((void**)&p_xgate,  g_xgate);
    cudaGetSymbolAddress((void**)&p_hhist,  g_hhist);
    cudaGetSymbolAddress((void**)&p_hh2,    g_hh2);
    cudaGetSymbolAddress((void**)&p_Wo2,    g_Wo2);

    const int smem_lstm = (8 * 4 * 512 + 32 * HPAD) * sizeof(float);   // 131584
    cudaFuncSetAttribute(lstm_kernel, cudaFuncAttributeMaxDynamicSharedMemorySize, smem_lstm);
    const int smem_tc = 2 * BUFSZ;                                      // 65536
    cudaFuncSetAttribute(mma_tc, cudaFuncAttributeMaxDynamicSharedMemorySize, smem_tc);

    // B-side split for logits (independent)
    split3_kernel<<<VPAD * 128 / 256, 256>>>(W_out, p_Wo2, VDIM, 1);

    // 1) frame embedding (rows b*80+t)
    {
        dim3 grid(EDIM / BN, MROWS / BM);
        gemm_kernel<<<grid, 256>>>(feats, FDIM, 0, W_frame, FDIM, 0,
                                   b_frame, nullptr, p_emb, MROWS, EDIM, FDIM, 0);
    }
    // 2) encoder x-gates -> transposed [s][n][b]
    {
        dim3 grid(GDIM / BN, MROWS / BM);
        gemm_kernel<<<grid, 256>>>(p_emb, EDIM, 1, W_ih, 2 * EDIM, 0,
                                   b_ih, b_hh, p_xgate, MROWS, GDIM, EDIM, 2);
    }
    // 3) decoder word embeddings (rows t*64+b)
    gather_dec_kernel<<<MROWS, 128>>>(labels, embed, p_decemb);
    // 4) decoder x-gates -> transposed, offset 80 steps
    {
        dim3 grid(GDIM / BN, MROWS / BM);
        gemm_kernel<<<grid, 256>>>(p_decemb, EDIM, 0, W_ih, 2 * EDIM, EDIM,
                                   b_ih, b_hh, p_xgate + (size_t)TSTEPS * GDIM * BATCH,
                                   MROWS, GDIM, EDIM, 2);
    }
    // 5) recurrence
    lstm_kernel<<<RCTAS, 256, smem_lstm>>>(W_hh, p_xgate, p_hhist);
    // 6) A-side split + tensor-core logits GEMM
    split3_kernel<<<MROWS * 128 / 256, 256>>>(p_hhist, p_hh2, MROWS, 2);
    {
        dim3 grid(VPAD / 128, MROWS / 128);
        mma_tc<<<grid, 256, smem_tc>>>(p_hh2, p_Wo2, b_out, out);
    }
}

// round 5
// speedup vs baseline: 2.1985x; 1.2745x over previous
#include <cuda_runtime.h>
#include <cuda_bf16.h>
#include <math.h>
#include <stdint.h>

#define TSTEPS 80
#define BATCH  64
#define FDIM   4096
#define EDIM   512
#define HDIM   512
#define VDIM   13000
#define VPAD   13056
#define GDIM   2048
#define NSTEPS 160
#define MROWS  5120
#define START_ID 1

// ---------------- scratch ----------------
__device__ __align__(16) __nv_bfloat16 g_feats2[(size_t)MROWS * 3 * FDIM];   // [hi|hi|lo]
__device__ __align__(16) __nv_bfloat16 g_Wf2   [(size_t)EDIM  * 3 * FDIM];   // [hi|lo|hi]
__device__ __align__(16) float         g_emb   [(size_t)MROWS * EDIM];        // t-major rows
__device__ __align__(16) __nv_bfloat16 g_emb2  [(size_t)MROWS * 3 * EDIM];
__device__ __align__(16) __nv_bfloat16 g_Wih2e [(size_t)GDIM  * 3 * EDIM];
__device__ __align__(16) __nv_bfloat16 g_Wih2d [(size_t)GDIM  * 3 * EDIM];
__device__ __align__(16) __nv_bfloat16 g_dece2 [(size_t)MROWS * 3 * EDIM];
__device__ __align__(16) float         g_xgate [(size_t)NSTEPS * BATCH * GDIM]; // [s*64+b][2048]
__device__ __align__(16) float         g_hhist [(size_t)MROWS * HDIM];          // t-major rows
__device__ __align__(16) __nv_bfloat16 g_hh2   [(size_t)MROWS * 3 * HDIM];
__device__ __align__(16) __nv_bfloat16 g_Wo2   [(size_t)VPAD  * 3 * HDIM];
__device__ __align__(16) float         g_hbuf  [2][BATCH * HDIM];
__device__ unsigned g_bar_cnt, g_bar_gen;

// ---------------- generic-PTX helpers ----------------
__device__ __forceinline__ uint32_t s2u(const void* p) {
    uint32_t a;
    asm("{ .reg .u64 t; cvta.to.shared.u64 t, %1; cvt.u32.u64 %0, t; }" : "=r"(a) : "l"(p));
    return a;
}
__device__ __forceinline__ void cpasync16(uint32_t dst, const void* src) {
    asm volatile("cp.async.cg.shared.global [%0], [%1], 16;" :: "r"(dst), "l"(src));
}
__device__ __forceinline__ void ldm4(uint32_t* d, uint32_t addr) {
    asm volatile("ldmatrix.sync.aligned.m8n8.x4.shared.b16 {%0,%1,%2,%3}, [%4];"
        : "=r"(d[0]), "=r"(d[1]), "=r"(d[2]), "=r"(d[3]) : "r"(addr));
}
__device__ __forceinline__ void mma16816(float* c, const uint32_t* a, const uint32_t* b) {
    asm volatile("mma.sync.aligned.m16n8k16.row.col.f32.bf16.bf16.f32 "
        "{%0,%1,%2,%3}, {%4,%5,%6,%7}, {%8,%9}, {%0,%1,%2,%3};"
        : "+f"(c[0]), "+f"(c[1]), "+f"(c[2]), "+f"(c[3])
        : "r"(a[0]), "r"(a[1]), "r"(a[2]), "r"(a[3]), "r"(b[0]), "r"(b[1]));
}
__device__ __forceinline__ void fma2(unsigned long long& acc,
                                     unsigned long long a, unsigned long long b) {
    asm("fma.rn.f32x2 %0, %1, %2, %0;" : "+l"(acc) : "l"(a), "l"(b));
}

// ---------------- fp32 -> 3-seg split-bf16 (K -> 3K) ----------------
// loSeg=2: [hi|hi|lo] (A side); loSeg=1: [hi|lo|hi] (B side). rows>=rows_src zeroed.
__global__ void split3_kernel(const float* __restrict__ src, int srcld, int coloff,
                              int K, int rows_src,
                              __nv_bfloat16* __restrict__ dst, int loSeg, long long total)
{
    long long i = (long long)blockIdx.x * 256 + threadIdx.x;
    if (i >= total) return;
    int kq = K >> 2;
    int r  = (int)(i / kq);
    int c4 = (int)(i % kq) << 2;
    __nv_bfloat16 hi[4], lo[4];
    if (r < rows_src) {
        float4 v = *(const float4*)(src + (size_t)r * srcld + coloff + c4);
        float vv[4] = {v.x, v.y, v.z, v.w};
#pragma unroll
        for (int j = 0; j < 4; j++) {
            hi[j] = __float2bfloat16(vv[j]);
            lo[j] = __float2bfloat16(vv[j] - __bfloat162float(hi[j]));
        }
    } else {
        __nv_bfloat16 z = __float2bfloat16(0.f);
#pragma unroll
        for (int j = 0; j < 4; j++) { hi[j] = z; lo[j] = z; }
    }
    __nv_bfloat16* d = dst + (size_t)r * (3 * K);
    int hOff = (loSeg == 2) ? K : 2 * K;
    int lOff = (loSeg == 2) ? 2 * K : K;
    *(uint64_t*)(d + c4)        = *(const uint64_t*)hi;
    *(uint64_t*)(d + hOff + c4) = *(const uint64_t*)hi;
    *(uint64_t*)(d + lOff + c4) = *(const uint64_t*)lo;
}

// ---------------- decoder gather, split-bf16, t-major rows ----------------
__global__ void gather2_kernel(const int* __restrict__ labels,
                               const float* __restrict__ embed,
                               __nv_bfloat16* __restrict__ dst)
{
    int r = blockIdx.x, t = r >> 6, b = r & 63;
    int id = (t == 0) ? START_ID : labels[b * TSTEPS + (t - 1)];
    int c4 = threadIdx.x * 4;
    float4 v = *(const float4*)(embed + (size_t)id * EDIM + c4);
    float vv[4] = {v.x, v.y, v.z, v.w};
    __nv_bfloat16 hi[4], lo[4];
#pragma unroll
    for (int j = 0; j < 4; j++) {
        hi[j] = __float2bfloat16(vv[j]);
        lo[j] = __float2bfloat16(vv[j] - __bfloat162float(hi[j]));
    }
    __nv_bfloat16* d = dst + (size_t)r * 1536;
    *(uint64_t*)(d + c4)        = *(const uint64_t*)hi;
    *(uint64_t*)(d + 512 + c4)  = *(const uint64_t*)hi;
    *(uint64_t*)(d + 1024 + c4) = *(const uint64_t*)lo;
}

// ---------------- mma.sync bf16 GEMM: C = A(M x kk) @ B(N x kk)^T + bias ----------------
// CTA tile 128x128, K-chunk 64, double-buffered cp.async, xor-swizzled smem.
// outMode: 0 = direct rows; 1 = logits remap (t-major r -> (b*80+t)); 2 = embed remap (b-major r -> t*64+b)
#define BUFSZ 32768

__device__ __forceinline__ void ld_chunk(uint32_t sbase,
    const __nv_bfloat16* __restrict__ A, const __nv_bfloat16* __restrict__ B,
    int m0, int n0, int kk, int c, int tid)
{
    const __nv_bfloat16* ap = A + (size_t)m0 * kk + c * 64;
    const __nv_bfloat16* bp = B + (size_t)n0 * kk + c * 64;
#pragma unroll
    for (int u = 0; u < 4; u++) {
        int idx = u * 256 + tid, r = idx >> 3, q = idx & 7;
        cpasync16(sbase + r * 128 + ((q ^ (r & 7)) << 4), ap + (size_t)r * kk + q * 8);
    }
#pragma unroll
    for (int u = 0; u < 4; u++) {
        int idx = u * 256 + tid, r = idx >> 3, q = idx & 7;
        cpasync16(sbase + 16384 + r * 128 + ((q ^ (r & 7)) << 4), bp + (size_t)r * kk + q * 8);
    }
}

__global__ __launch_bounds__(256) void mma_tc(
    const __nv_bfloat16* __restrict__ A, const __nv_bfloat16* __restrict__ B,
    const float* __restrict__ bias1, const float* __restrict__ bias2,
    float* __restrict__ C, int kk, int Nreal, int ldc, int outMode)
{
    extern __shared__ char smc[];
    const uint32_t sbase = s2u(smc);
    const int tid = threadIdx.x, lane = tid & 31, wid = tid >> 5;
    const int wm = wid & 3, wn = wid >> 2;        // warp tile 32 x 64
    const int n0 = blockIdx.x * 128, m0 = blockIdx.y * 128;
    const int NC = kk >> 6;

    float acc[2][8][4];
#pragma unroll
    for (int a = 0; a < 2; a++)
#pragma unroll
        for (int b = 0; b < 8; b++)
#pragma unroll
            for (int d = 0; d < 4; d++) acc[a][b][d] = 0.f;

    ld_chunk(sbase, A, B, m0, n0, kk, 0, tid);
    asm volatile("cp.async.commit_group;" ::: "memory");

    for (int c = 0; c < NC; c++) {
        if (c + 1 < NC) {
            ld_chunk(sbase + ((c + 1) & 1) * BUFSZ, A, B, m0, n0, kk, c + 1, tid);
            asm volatile("cp.async.commit_group;" ::: "memory");
            asm volatile("cp.async.wait_group 1;" ::: "memory");
        } else {
            asm volatile("cp.async.wait_group 0;" ::: "memory");
        }
        __syncthreads();

        const uint32_t sa = sbase + (c & 1) * BUFSZ;
        const uint32_t sb = sa + 16384;
#pragma unroll
        for (int ks = 0; ks < 4; ks++) {
            uint32_t af[2][4];
#pragma unroll
            for (int mt = 0; mt < 2; mt++) {
                int r = wm * 32 + mt * 16 + (lane & 15);
                int q = 2 * ks + (lane >> 4);
                ldm4(af[mt], sa + r * 128 + ((q ^ (r & 7)) << 4));
            }
            uint32_t bf[4][4];
#pragma unroll
            for (int bp2 = 0; bp2 < 4; bp2++) {
                int r = wn * 64 + (bp2 * 2 + (lane >> 4)) * 8 + (lane & 7);
                int q = 2 * ks + ((lane >> 3) & 1);
                ldm4(bf[bp2], sb + r * 128 + ((q ^ (r & 7)) << 4));
            }
#pragma unroll
            for (int mt = 0; mt < 2; mt++)
#pragma unroll
                for (int nt = 0; nt < 8; nt++)
                    mma16816(acc[mt][nt], af[mt], &bf[nt >> 1][(nt & 1) * 2]);
        }
        __syncthreads();
    }

    const int mb = m0 + wm * 32, nb = n0 + wn * 64;
#pragma unroll
    for (int mt = 0; mt < 2; mt++)
#pragma unroll
        for (int half = 0; half < 2; half++) {
            int r = mb + mt * 16 + (lane >> 2) + half * 8;
            int rr;
            if (outMode == 1)      rr = (r & 63) * 80 + (r >> 6);
            else if (outMode == 2) rr = (r % 80) * 64 + (r / 80);
            else                   rr = r;
            float* op = C + (size_t)rr * ldc;
#pragma unroll
            for (int nt = 0; nt < 8; nt++) {
                int cb = nb + nt * 8 + (lane & 3) * 2;
                if (cb < Nreal) {
                    float2 bv = *(const float2*)(bias1 + cb);
                    if (bias2) {
                        float2 b2 = *(const float2*)(bias2 + cb);
                        bv.x += b2.x; bv.y += b2.y;
                    }
                    float2 v;
                    v.x = acc[mt][nt][half * 2 + 0] + bv.x;
                    v.y = acc[mt][nt][half * 2 + 1] + bv.y;
                    *(float2*)(op + cb) = v;
                }
            }
        }
}

// ---------------- persistent LSTM (f32x2, k-parity accumulators) ----------------
#define RCTAS 128
#define HPAD  516

__device__ __forceinline__ void grid_sync()
{
    __syncthreads();
    if (threadIdx.x == 0) {
        __threadfence();
        unsigned gen = *(volatile unsigned*)&g_bar_gen;
        if (atomicAdd(&g_bar_cnt, 1u) == RCTAS - 1) {
            *(volatile unsigned*)&g_bar_cnt = 0u;
            __threadfence();
            *(volatile unsigned*)&g_bar_gen = gen + 1u;
        } else {
            while (*(volatile unsigned*)&g_bar_gen == gen) { }
        }
    }
    __syncthreads();
}
__device__ __forceinline__ float sigf(float x) { return 1.f / (1.f + expf(-x)); }

__global__ __launch_bounds__(256, 1) void lstm_kernel(
    const float* __restrict__ Whh, const float* __restrict__ xg,
    float* __restrict__ hhist)
{
    extern __shared__ float sm[];
    float* ws = sm;                       // [8 hu][4 gate][512 k]
    float* hs = sm + 8 * 4 * 512;         // [32 b][HPAD]
    float* xs = hs + 32 * HPAD;           // [4 g][32 b][9]

    const int tid = threadIdx.x;
    const int b_l = tid & 31, hu_l = tid >> 5;
    const int ct_b = blockIdx.x & 1, ct_h = blockIdx.x >> 1;
    const int hu = ct_h * 8 + hu_l, b = ct_b * 32 + b_l;

    for (int i = tid; i < 8 * 4 * 512; i += 256) {
        int h = i >> 11, g = (i >> 9) & 3, k = i & 511;
        ws[i] = Whh[(size_t)(g * 512 + ct_h * 8 + h) * 512 + k];
    }
    {
        int i = blockIdx.x * 256 + tid;   // exactly covers 32768
        g_hbuf[0][i] = 0.f;
    }
    float cc = 0.f;
    grid_sync();

    // x staging indices: thread -> (gate, batch, half of 8 floats)
    const int sg = tid >> 6, sb2 = (tid >> 1) & 31, shalf = tid & 1;

    int cur = 0;
    for (int s = 0; s < NSTEPS; s++) {
        // stage x slice (coalesced): rows s*64 + ct_b*32 + sb2, cols sg*512 + ct_h*8 + shalf*4
        {
            const float* xr = xg + (size_t)(s * 64 + ct_b * 32 + sb2) * GDIM
                            + sg * 512 + ct_h * 8 + shalf * 4;
            float4 xv = *(const float4*)xr;
            float* d = xs + sg * 288 + sb2 * 9 + shalf * 4;
            d[0] = xv.x; d[1] = xv.y; d[2] = xv.z; d[3] = xv.w;
        }
        // stage this CTA's 32-batch h slice
        const float4* src = (const float4*)(g_hbuf[cur] + (size_t)ct_b * 32 * 512);
#pragma unroll
        for (int j = 0; j < 16; j++) {
            int idx = tid + j * 256;
            float4 v = __ldcg(src + idx);
            int bb = idx >> 7, kq = (idx & 127) << 2;
            *(float4*)(hs + bb * HPAD + kq) = v;
        }
        __syncthreads();

        float x0 = xs[0 * 288 + b_l * 9 + hu_l];
        float x1 = xs[1 * 288 + b_l * 9 + hu_l];
        float x2 = xs[2 * 288 + b_l * 9 + hu_l];
        float x3 = xs[3 * 288 + b_l * 9 + hu_l];

        unsigned long long a0 = 0ull, a1 = 0ull, a2 = 0ull, a3 = 0ull;
        const longlong2* hp = (const longlong2*)(hs + b_l * HPAD);
        const longlong2* w0 = (const longlong2*)(ws + (hu_l * 4 + 0) * 512);
        const longlong2* w1 = (const longlong2*)(ws + (hu_l * 4 + 1) * 512);
        const longlong2* w2 = (const longlong2*)(ws + (hu_l * 4 + 2) * 512);
        const longlong2* w3 = (const longlong2*)(ws + (hu_l * 4 + 3) * 512);
#pragma unroll 4
        for (int k4 = 0; k4 < 128; k4++) {
            longlong2 h2 = hp[k4];
            longlong2 w;
            w = w0[k4];
            fma2(a0, (unsigned long long)h2.x, (unsigned long long)w.x);
            fma2(a0, (unsigned long long)h2.y, (unsigned long long)w.y);
            w = w1[k4];
            fma2(a1, (unsigned long long)h2.x, (unsigned long long)w.x);
            fma2(a1, (unsigned long long)h2.y, (unsigned long long)w.y);
            w = w2[k4];
            fma2(a2, (unsigned long long)h2.x, (unsigned long long)w.x);
            fma2(a2, (unsigned long long)h2.y, (unsigned long long)w.y);
            w = w3[k4];
            fma2(a3, (unsigned long long)h2.x, (unsigned long long)w.x);
            fma2(a3, (unsigned long long)h2.y, (unsigned long long)w.y);
        }
        float lo, hi, gi, gf, gg, go;
        asm("mov.b64 {%0,%1}, %2;" : "=f"(lo), "=f"(hi) : "l"(a0)); gi = lo + hi + x0;
        asm("mov.b64 {%0,%1}, %2;" : "=f"(lo), "=f"(hi) : "l"(a1)); gf = lo + hi + x1;
        asm("mov.b64 {%0,%1}, %2;" : "=f"(lo), "=f"(hi) : "l"(a2)); gg = lo + hi + x2;
        asm("mov.b64 {%0,%1}, %2;" : "=f"(lo), "=f"(hi) : "l"(a3)); go = lo + hi + x3;

        float iv = sigf(gi), fv = sigf(gf), gv = tanhf(gg), ov = sigf(go);
        cc = fv * cc + iv * gv;
        float hv = ov * tanhf(cc);

        g_hbuf[cur ^ 1][(size_t)b * 512 + hu] = hv;
        if (s >= TSTEPS)
            hhist[(size_t)((s - TSTEPS) * 64 + b) * 512 + hu] = hv;

        grid_sync();
        cur ^= 1;
    }
}

// ---------------- launch ----------------
extern "C" void kernel_launch(void* const* d_in, const int* in_sizes, int n_in,
                              void* d_out, int out_size)
{
    const float* feats   = (const float*)d_in[0];
    const int*   labels  = (const int*)  d_in[1];
    const float* W_frame = (const float*)d_in[2];
    const float* b_frame = (const float*)d_in[3];
    const float* embed   = (const float*)d_in[4];
    const float* W_ih    = (const float*)d_in[5];
    const float* W_hh    = (const float*)d_in[6];
    const float* b_ih    = (const float*)d_in[7];
    const float* b_hh    = (const float*)d_in[8];
    const float* W_out   = (const float*)d_in[9];
    const float* b_out   = (const float*)d_in[10];
    float* out = (float*)d_out;

    float *p_emb, *p_xgate, *p_hhist;
    __nv_bfloat16 *p_feats2, *p_Wf2, *p_emb2, *p_Wih2e, *p_Wih2d, *p_dece2, *p_hh2, *p_Wo2;
    cudaGetSymbolAddress((void**)&p_emb,    g_emb);
    cudaGetSymbolAddress((void**)&p_xgate,  g_xgate);
    cudaGetSymbolAddress((void**)&p_hhist,  g_hhist);
    cudaGetSymbolAddress((void**)&p_feats2, g_feats2);
    cudaGetSymbolAddress((void**)&p_Wf2,    g_Wf2);
    cudaGetSymbolAddress((void**)&p_emb2,   g_emb2);
    cudaGetSymbolAddress((void**)&p_Wih2e,  g_Wih2e);
    cudaGetSymbolAddress((void**)&p_Wih2d,  g_Wih2d);
    cudaGetSymbolAddress((void**)&p_dece2,  g_dece2);
    cudaGetSymbolAddress((void**)&p_hh2,    g_hh2);
    cudaGetSymbolAddress((void**)&p_Wo2,    g_Wo2);

    const int smem_lstm = (8 * 4 * 512 + 32 * HPAD + 4 * 288) * sizeof(float);
    cudaFuncSetAttribute(lstm_kernel, cudaFuncAttributeMaxDynamicSharedMemorySize, smem_lstm);
    const int smem_tc = 2 * BUFSZ;
    cudaFuncSetAttribute(mma_tc, cudaFuncAttributeMaxDynamicSharedMemorySize, smem_tc);

    // ---- splits (inputs) ----
    {   // feats: 5120 x 4096, A-side
        long long tot = (long long)MROWS * (FDIM / 4);
        split3_kernel<<<(unsigned)((tot + 255) / 256), 256>>>(feats, FDIM, 0, FDIM, MROWS, p_feats2, 2, tot);
    }
    {   // W_frame: 512 x 4096, B-side
        long long tot = (long long)EDIM * (FDIM / 4);
        split3_kernel<<<(unsigned)((tot + 255) / 256), 256>>>(W_frame, FDIM, 0, FDIM, EDIM, p_Wf2, 1, tot);
    }
    {   // W_ih encoder cols [0,512), decoder cols [512,1024), B-side
        long long tot = (long long)GDIM * (EDIM / 4);
        split3_kernel<<<(unsigned)((tot + 255) / 256), 256>>>(W_ih, 2 * EDIM, 0,    EDIM, GDIM, p_Wih2e, 1, tot);
        split3_kernel<<<(unsigned)((tot + 255) / 256), 256>>>(W_ih, 2 * EDIM, EDIM, EDIM, GDIM, p_Wih2d, 1, tot);
    }
    {   // W_out: 13056 x 512, B-side (rows >= 13000 zeroed)
        long long tot = (long long)VPAD * (HDIM / 4);
        split3_kernel<<<(unsigned)((tot + 255) / 256), 256>>>(W_out, HDIM, 0, HDIM, VDIM, p_Wo2, 1, tot);
    }
    // decoder word embeddings (t-major, split)
    gather2_kernel<<<MROWS, 128>>>(labels, embed, p_dece2);

    // 1) frame embedding: emb(t-major) = feats @ W_frame^T + b_frame   [K=12288]
    {
        dim3 grid(EDIM / 128, MROWS / 128);
        mma_tc<<<grid, 256, smem_tc>>>(p_feats2, p_Wf2, b_frame, nullptr,
                                       p_emb, 3 * FDIM, EDIM, EDIM, 2);
    }
    // split emb (A-side)
    {
        long long tot = (long long)MROWS * (EDIM / 4);
        split3_kernel<<<(unsigned)((tot + 255) / 256), 256>>>(p_emb, EDIM, 0, EDIM, MROWS, p_emb2, 2, tot);
    }
    // 2) encoder x-gates: rows s*64+b, cols 2048   [K=1536]
    {
        dim3 grid(GDIM / 128, MROWS / 128);
        mma_tc<<<grid, 256, smem_tc>>>(p_emb2, p_Wih2e, b_ih, b_hh,
                                       p_xgate, 3 * EDIM, GDIM, GDIM, 0);
    }
    // 3) decoder x-gates: rows (80+t)*64+b
    {
        dim3 grid(GDIM / 128, MROWS / 128);
        mma_tc<<<grid, 256, smem_tc>>>(p_dece2, p_Wih2d, b_ih, b_hh,
                                       p_xgate + (size_t)MROWS * GDIM, 3 * EDIM, GDIM, GDIM, 0);
    }
    // 4) recurrence
    lstm_kernel<<<RCTAS, 256, smem_lstm>>>(W_hh, p_xgate, p_hhist);
    // 5) A-side split + logits GEMM   [K=1536]
    {
        long long tot = (long long)MROWS * (HDIM / 4);
        split3_kernel<<<(unsigned)((tot + 255) / 256), 256>>>(p_hhist, HDIM, 0, HDIM, MROWS, p_hh2, 2, tot);
    }
    {
        dim3 grid(VPAD / 128, MROWS / 128);
        mma_tc<<<grid, 256, smem_tc>>>(p_hh2, p_Wo2, b_out, nullptr,
                                       out, 3 * HDIM, VDIM, VDIM, 1);
    }
}